// round 3
// baseline (speedup 1.0000x reference)
#include <cuda_runtime.h>
#include <cuda_bf16.h>

// ---------------------------------------------------------------------------
// FreeConvNetwork: 3 locally-connected layers + linear head, B = 8192, fp32.
//   LL1: (B,1,28,28)  -> (B,32,13,13), K=3, s=2
//   LL2: (B,32,13,13) -> (B,64,6,6),   K=3, s=2   == 36 GEMMs M=8192,N=64,K=288
//   LL3: (B,64,6,6)   -> (B,128,4,4),  K=3, s=1   == 16 GEMMs M=8192,N=128,K=576
//   LIN: (B,2048) @ (2048,10)^T
// All activations stored feature-major, batch-innermost: act[f * B + b].
// Patch feature index k = c*9 + di*3 + dj (JAX conv_general_dilated_patches order).
// ---------------------------------------------------------------------------

#define BATCH 8192

// Scratch (device globals: allocation-free per harness rules)
__device__ float g_xT [784        * BATCH];          // (28*28, B)
__device__ float g_h1 [32  * 169  * BATCH];          // (c*169 + i*13+j, B)
__device__ float g_h2 [64  * 36   * BATCH];          // (c*36  + i*6 +j, B)
__device__ float g_h3 [2048       * BATCH];          // (c*16  + i*4 +j, B)
__device__ float g_W2T[36 * 288 * 64];               // (loc, k, o)
__device__ float g_W3T[16 * 576 * 128];              // (loc, k, o)

// ---------------------------------------------------------------------------
// x (B,784) -> xT (784,B), tiled transpose
// ---------------------------------------------------------------------------
__global__ void transpose_x_k(const float* __restrict__ x) {
    __shared__ float tile[32][33];
    int c  = blockIdx.x * 32 + threadIdx.x;   // pixel index in input
    int r0 = blockIdx.y * 32;                 // batch base
    #pragma unroll
    for (int i = threadIdx.y; i < 32; i += 8) {
        int r = r0 + i;
        tile[i][threadIdx.x] = (c < 784) ? x[r * 784 + c] : 0.f;
    }
    __syncthreads();
    int oc  = r0 + threadIdx.x;               // batch
    int or0 = blockIdx.x * 32;                // pixel
    #pragma unroll
    for (int i = threadIdx.y; i < 32; i += 8) {
        int orow = or0 + i;
        if (orow < 784) g_xT[orow * BATCH + oc] = tile[threadIdx.x][i];
    }
}

// ---------------------------------------------------------------------------
// W (O, K2, L) -> WT (L, K2, O)   [L = oh*ow locations]
// ---------------------------------------------------------------------------
__global__ void wtrans2_k(const float* __restrict__ W) {
    const int O = 64, K2 = 288, L = 36;
    int idx = blockIdx.x * blockDim.x + threadIdx.x;
    if (idx >= O * K2 * L) return;
    int o = idx % O; int k = (idx / O) % K2; int l = idx / (O * K2);
    g_W2T[idx] = W[(o * K2 + k) * L + l];
}
__global__ void wtrans3_k(const float* __restrict__ W) {
    const int O = 128, K2 = 576, L = 16;
    int idx = blockIdx.x * blockDim.x + threadIdx.x;
    if (idx >= O * K2 * L) return;
    int o = idx % O; int k = (idx / O) % K2; int l = idx / (O * K2);
    g_W3T[idx] = W[(o * K2 + k) * L + l];
}

// ---------------------------------------------------------------------------
// LL1: tiny layer. grid = (169 locations, B/256). One thread = one batch elem.
// ---------------------------------------------------------------------------
__global__ __launch_bounds__(256) void ll1_k(const float* __restrict__ W1,
                                             const float* __restrict__ b1) {
    int loc = blockIdx.x;
    int i = loc / 13, j = loc % 13;
    int b = blockIdx.y * 256 + threadIdx.x;

    __shared__ float ws[32 * 9];
    __shared__ float bs[32];
    for (int t = threadIdx.x; t < 32 * 9; t += 256) {
        int o = t / 9, k = t % 9;
        ws[t] = W1[(o * 9 + k) * 169 + loc];
    }
    if (threadIdx.x < 32) bs[threadIdx.x] = b1[threadIdx.x * 169 + loc];
    __syncthreads();

    float v[9];
    #pragma unroll
    for (int k = 0; k < 9; k++) {
        int di = k / 3, dj = k % 3;
        v[k] = g_xT[((2 * i + di) * 28 + (2 * j + dj)) * BATCH + b];
    }
    #pragma unroll
    for (int o = 0; o < 32; o++) {
        float acc = bs[o];
        #pragma unroll
        for (int k = 0; k < 9; k++) acc = fmaf(ws[o * 9 + k], v[k], acc);
        g_h1[(o * 169 + loc) * BATCH + b] = fmaxf(acc, 0.f);
    }
}

// ---------------------------------------------------------------------------
// LL2: per-location GEMM. M=8192, N=64, K=288.
// grid = (36, 64). block 256 = 16x16, thread tile 8(m) x 4(n), BK=8.
// ---------------------------------------------------------------------------
__global__ __launch_bounds__(256) void ll2_k(const float* __restrict__ b2) {
    const int BK = 8;
    int loc = blockIdx.x;
    int i = loc / 6, j = loc % 6;
    int m0 = blockIdx.y * 128;

    __shared__ __align__(16) float As[BK][128];
    __shared__ __align__(16) float Ws[BK][64];
    __shared__ int rowoff[288];

    int tid = threadIdx.x;
    for (int k = tid; k < 288; k += 256) {
        int c = k / 9, r = (k % 9) / 3, cc = k % 3;
        rowoff[k] = (c * 169 + (2 * i + r) * 13 + (2 * j + cc)) * BATCH;
    }
    __syncthreads();

    int tx = tid % 16;   // n: 4 outputs
    int ty = tid / 16;   // m: 8 batch
    float acc[8][4];
    #pragma unroll
    for (int mm = 0; mm < 8; mm++)
        #pragma unroll
        for (int nn = 0; nn < 4; nn++) acc[mm][nn] = 0.f;

    const float* wbase = g_W2T + loc * 288 * 64;

    for (int k0 = 0; k0 < 288; k0 += BK) {
        // A: 128x8 = 1024 elems, 4 per thread
        #pragma unroll
        for (int kk = 0; kk < BK; kk += 2) {
            int k = k0 + kk + tid / 128;
            int m = tid % 128;
            As[kk + tid / 128][m] = g_h1[rowoff[k] + m0 + m];
        }
        // W: 8x64 = 512 elems, 2 per thread
        #pragma unroll
        for (int kk = 0; kk < BK; kk += 4) {
            int k = k0 + kk + tid / 64;
            int n = tid % 64;
            Ws[kk + tid / 64][n] = wbase[k * 64 + n];
        }
        __syncthreads();
        #pragma unroll
        for (int kk = 0; kk < BK; kk++) {
            float4 a0 = *(const float4*)&As[kk][ty * 8];
            float4 a1 = *(const float4*)&As[kk][ty * 8 + 4];
            float4 w0 = *(const float4*)&Ws[kk][tx * 4];
            float av[8] = {a0.x, a0.y, a0.z, a0.w, a1.x, a1.y, a1.z, a1.w};
            float wv[4] = {w0.x, w0.y, w0.z, w0.w};
            #pragma unroll
            for (int mm = 0; mm < 8; mm++)
                #pragma unroll
                for (int nn = 0; nn < 4; nn++)
                    acc[mm][nn] = fmaf(av[mm], wv[nn], acc[mm][nn]);
        }
        __syncthreads();
    }
    // epilogue: relu(acc + bias) -> h2[(o*36+loc)*B + b], float4 along batch
    #pragma unroll
    for (int nn = 0; nn < 4; nn++) {
        int o = tx * 4 + nn;
        float bias = b2[o * 36 + loc];
        float4 s0, s1;
        s0.x = fmaxf(acc[0][nn] + bias, 0.f);
        s0.y = fmaxf(acc[1][nn] + bias, 0.f);
        s0.z = fmaxf(acc[2][nn] + bias, 0.f);
        s0.w = fmaxf(acc[3][nn] + bias, 0.f);
        s1.x = fmaxf(acc[4][nn] + bias, 0.f);
        s1.y = fmaxf(acc[5][nn] + bias, 0.f);
        s1.z = fmaxf(acc[6][nn] + bias, 0.f);
        s1.w = fmaxf(acc[7][nn] + bias, 0.f);
        float* dst = &g_h2[(o * 36 + loc) * BATCH + m0 + ty * 8];
        *(float4*)dst       = s0;
        *(float4*)(dst + 4) = s1;
    }
}

// ---------------------------------------------------------------------------
// LL3: per-location GEMM. M=8192, N=128, K=576.
// grid = (16, 64). block 256 = 16x16, thread tile 8x8, BK=8.
// ---------------------------------------------------------------------------
__global__ __launch_bounds__(256) void ll3_k(const float* __restrict__ b3) {
    const int BK = 8;
    int loc = blockIdx.x;
    int i = loc / 4, j = loc % 4;
    int m0 = blockIdx.y * 128;

    __shared__ __align__(16) float As[BK][128];
    __shared__ __align__(16) float Ws[BK][128];
    __shared__ int rowoff[576];

    int tid = threadIdx.x;
    for (int k = tid; k < 576; k += 256) {
        int c = k / 9, r = (k % 9) / 3, cc = k % 3;
        rowoff[k] = (c * 36 + (i + r) * 6 + (j + cc)) * BATCH;
    }
    __syncthreads();

    int tx = tid % 16;   // n: 8 outputs
    int ty = tid / 16;   // m: 8 batch
    float acc[8][8];
    #pragma unroll
    for (int mm = 0; mm < 8; mm++)
        #pragma unroll
        for (int nn = 0; nn < 8; nn++) acc[mm][nn] = 0.f;

    const float* wbase = g_W3T + loc * 576 * 128;

    for (int k0 = 0; k0 < 576; k0 += BK) {
        #pragma unroll
        for (int kk = 0; kk < BK; kk += 2) {
            int k = k0 + kk + tid / 128;
            int m = tid % 128;
            As[kk + tid / 128][m] = g_h2[rowoff[k] + m0 + m];
        }
        #pragma unroll
        for (int kk = 0; kk < BK; kk += 2) {
            int k = k0 + kk + tid / 128;
            int n = tid % 128;
            Ws[kk + tid / 128][n] = wbase[k * 128 + n];
        }
        __syncthreads();
        #pragma unroll
        for (int kk = 0; kk < BK; kk++) {
            float4 a0 = *(const float4*)&As[kk][ty * 8];
            float4 a1 = *(const float4*)&As[kk][ty * 8 + 4];
            float4 w0 = *(const float4*)&Ws[kk][tx * 8];
            float4 w1 = *(const float4*)&Ws[kk][tx * 8 + 4];
            float av[8] = {a0.x, a0.y, a0.z, a0.w, a1.x, a1.y, a1.z, a1.w};
            float wv[8] = {w0.x, w0.y, w0.z, w0.w, w1.x, w1.y, w1.z, w1.w};
            #pragma unroll
            for (int mm = 0; mm < 8; mm++)
                #pragma unroll
                for (int nn = 0; nn < 8; nn++)
                    acc[mm][nn] = fmaf(av[mm], wv[nn], acc[mm][nn]);
        }
        __syncthreads();
    }
    // epilogue: f = o*16 + loc (channel-major flatten), relu(acc + bias)
    #pragma unroll
    for (int nn = 0; nn < 8; nn++) {
        int o = tx * 8 + nn;
        float bias = b3[o * 16 + loc];
        float4 s0, s1;
        s0.x = fmaxf(acc[0][nn] + bias, 0.f);
        s0.y = fmaxf(acc[1][nn] + bias, 0.f);
        s0.z = fmaxf(acc[2][nn] + bias, 0.f);
        s0.w = fmaxf(acc[3][nn] + bias, 0.f);
        s1.x = fmaxf(acc[4][nn] + bias, 0.f);
        s1.y = fmaxf(acc[5][nn] + bias, 0.f);
        s1.z = fmaxf(acc[6][nn] + bias, 0.f);
        s1.w = fmaxf(acc[7][nn] + bias, 0.f);
        float* dst = &g_h3[(o * 16 + loc) * BATCH + m0 + ty * 8];
        *(float4*)dst       = s0;
        *(float4*)(dst + 4) = s1;
    }
}

// ---------------------------------------------------------------------------
// Linear head: (B,2048) @ (2048,10)^T + bias, relu.
// grid = B/32. 256 threads: 32 batch x 8 split-K groups; smem reduction.
// ---------------------------------------------------------------------------
__global__ __launch_bounds__(256) void lin_k(const float* __restrict__ Wl,
                                             const float* __restrict__ blin,
                                             float* __restrict__ out) {
    const int CHUNK = 512;                     // f per smem chunk
    __shared__ float Wls[CHUNK * 10];          // 20 KB
    __shared__ float sacc[8][32][10];          // 10 KB

    int m0  = blockIdx.x * 32;
    int tid = threadIdx.x;
    int bl_ = tid % 32;                        // batch within block
    int g   = tid / 32;                        // split-K group (== warp id)

    float acc[10];
    #pragma unroll
    for (int t = 0; t < 10; t++) acc[t] = 0.f;

    for (int c = 0; c < 4; c++) {
        __syncthreads();
        for (int idx = tid; idx < CHUNK * 10; idx += 256) {
            int fl = idx / 10, t = idx % 10;
            Wls[idx] = Wl[t * 2048 + c * CHUNK + fl];
        }
        __syncthreads();
        int fbase = g * (CHUNK / 8);           // 64 f per group per chunk
        #pragma unroll 4
        for (int fl = fbase; fl < fbase + CHUNK / 8; fl++) {
            int f = c * CHUNK + fl;
            float v = g_h3[f * BATCH + m0 + bl_];
            const float* w = &Wls[fl * 10];
            #pragma unroll
            for (int t = 0; t < 10; t++) acc[t] = fmaf(v, w[t], acc[t]);
        }
    }
    #pragma unroll
    for (int t = 0; t < 10; t++) sacc[g][bl_][t] = acc[t];
    __syncthreads();
    // 320 (batch, class) pairs per block; blockDim = 256, so stride the loop.
    for (int t2 = tid; t2 < 320; t2 += 256) {
        int bb = t2 / 10, t = t2 % 10;
        float s = blin[t];
        #pragma unroll
        for (int gg = 0; gg < 8; gg++) s += sacc[gg][bb][t];
        out[(m0 + bb) * 10 + t] = fmaxf(s, 0.f);
    }
}

// ---------------------------------------------------------------------------
extern "C" void kernel_launch(void* const* d_in, const int* in_sizes, int n_in,
                              void* d_out, int out_size) {
    const float* x  = (const float*)d_in[0];
    const float* W1 = (const float*)d_in[1];
    const float* b1 = (const float*)d_in[2];
    const float* W2 = (const float*)d_in[3];
    const float* b2 = (const float*)d_in[4];
    const float* W3 = (const float*)d_in[5];
    const float* b3 = (const float*)d_in[6];
    const float* Wl = (const float*)d_in[7];
    const float* bl = (const float*)d_in[8];
    float* out = (float*)d_out;

    transpose_x_k<<<dim3(25, 256), dim3(32, 8)>>>(x);
    wtrans2_k<<<(64 * 288 * 36 + 255) / 256, 256>>>(W2);
    wtrans3_k<<<(128 * 576 * 16 + 255) / 256, 256>>>(W3);
    ll1_k<<<dim3(169, 32), 256>>>(W1, b1);
    ll2_k<<<dim3(36, 64), 256>>>(b2);
    ll3_k<<<dim3(16, 64), 256>>>(b3);
    lin_k<<<256, 256>>>(Wl, bl, out);
}

// round 4
// speedup vs baseline: 1.0022x; 1.0022x over previous
#include <cuda_runtime.h>
#include <cuda_bf16.h>

// ---------------------------------------------------------------------------
// FreeConvNetwork: 3 locally-connected layers + linear head, B = 8192, fp32.
//   LL1: (B,1,28,28)  -> (B,32,13,13), K=3, s=2
//   LL2: (B,32,13,13) -> (B,64,6,6),   K=3, s=2   == 36 GEMMs M=8192,N=64,K=288
//   LL3: (B,64,6,6)   -> (B,128,4,4),  K=3, s=1   == 16 GEMMs M=8192,N=128,K=576
//   LIN: (B,2048) @ (2048,10)^T
// All activations stored feature-major, batch-innermost: act[f * B + b].
// Patch feature index k = c*9 + di*3 + dj (JAX conv_general_dilated_patches order).
// ---------------------------------------------------------------------------

#define BATCH 8192

// Scratch (device globals: allocation-free per harness rules)
__device__ float g_xT [784        * BATCH];          // (28*28, B)
__device__ float g_h1 [32  * 169  * BATCH];          // (c*169 + i*13+j, B)
__device__ float g_h2 [64  * 36   * BATCH];          // (c*36  + i*6 +j, B)
__device__ float g_h3 [2048       * BATCH];          // (c*16  + i*4 +j, B)
__device__ float g_W2T[36 * 288 * 64];               // (loc, k, o)
__device__ float g_W3T[16 * 576 * 128];              // (loc, k, o)

// ---------------------------------------------------------------------------
// x (B,784) -> xT (784,B), tiled transpose
// ---------------------------------------------------------------------------
__global__ void transpose_x_k(const float* __restrict__ x) {
    __shared__ float tile[32][33];
    int c  = blockIdx.x * 32 + threadIdx.x;   // pixel index in input
    int r0 = blockIdx.y * 32;                 // batch base
    #pragma unroll
    for (int i = threadIdx.y; i < 32; i += 8) {
        int r = r0 + i;
        tile[i][threadIdx.x] = (c < 784) ? x[r * 784 + c] : 0.f;
    }
    __syncthreads();
    int oc  = r0 + threadIdx.x;               // batch
    int or0 = blockIdx.x * 32;                // pixel
    #pragma unroll
    for (int i = threadIdx.y; i < 32; i += 8) {
        int orow = or0 + i;
        if (orow < 784) g_xT[orow * BATCH + oc] = tile[threadIdx.x][i];
    }
}

// ---------------------------------------------------------------------------
// W (O, K2, L) -> WT (L, K2, O)   [L = oh*ow locations]
// ---------------------------------------------------------------------------
__global__ void wtrans2_k(const float* __restrict__ W) {
    const int O = 64, K2 = 288, L = 36;
    int idx = blockIdx.x * blockDim.x + threadIdx.x;
    if (idx >= O * K2 * L) return;
    int o = idx % O; int k = (idx / O) % K2; int l = idx / (O * K2);
    g_W2T[idx] = W[(o * K2 + k) * L + l];
}
__global__ void wtrans3_k(const float* __restrict__ W) {
    const int O = 128, K2 = 576, L = 16;
    int idx = blockIdx.x * blockDim.x + threadIdx.x;
    if (idx >= O * K2 * L) return;
    int o = idx % O; int k = (idx / O) % K2; int l = idx / (O * K2);
    g_W3T[idx] = W[(o * K2 + k) * L + l];
}

// ---------------------------------------------------------------------------
// LL1: tiny layer. grid = (169 locations, B/256). One thread = one batch elem.
// ---------------------------------------------------------------------------
__global__ __launch_bounds__(256) void ll1_k(const float* __restrict__ W1,
                                             const float* __restrict__ b1) {
    int loc = blockIdx.x;
    int i = loc / 13, j = loc % 13;
    int b = blockIdx.y * 256 + threadIdx.x;

    __shared__ float ws[32 * 9];
    __shared__ float bs[32];
    for (int t = threadIdx.x; t < 32 * 9; t += 256) {
        int o = t / 9, k = t % 9;
        ws[t] = W1[(o * 9 + k) * 169 + loc];
    }
    if (threadIdx.x < 32) bs[threadIdx.x] = b1[threadIdx.x * 169 + loc];
    __syncthreads();

    float v[9];
    #pragma unroll
    for (int k = 0; k < 9; k++) {
        int di = k / 3, dj = k % 3;
        v[k] = g_xT[((2 * i + di) * 28 + (2 * j + dj)) * BATCH + b];
    }
    #pragma unroll
    for (int o = 0; o < 32; o++) {
        float acc = bs[o];
        #pragma unroll
        for (int k = 0; k < 9; k++) acc = fmaf(ws[o * 9 + k], v[k], acc);
        g_h1[(o * 169 + loc) * BATCH + b] = fmaxf(acc, 0.f);
    }
}

// ---------------------------------------------------------------------------
// LL2: per-location GEMM. M=8192, N=64, K=288.
// grid = (36, 64). block 256 = 16x16, thread tile 8(m) x 4(n), BK=8.
// ---------------------------------------------------------------------------
__global__ __launch_bounds__(256) void ll2_k(const float* __restrict__ b2) {
    const int BK = 8;
    int loc = blockIdx.x;
    int i = loc / 6, j = loc % 6;
    int m0 = blockIdx.y * 128;

    __shared__ __align__(16) float As[BK][128];
    __shared__ __align__(16) float Ws[BK][64];
    __shared__ int rowoff[288];

    int tid = threadIdx.x;
    for (int k = tid; k < 288; k += 256) {
        int c = k / 9, r = (k % 9) / 3, cc = k % 3;
        rowoff[k] = (c * 169 + (2 * i + r) * 13 + (2 * j + cc)) * BATCH;
    }
    __syncthreads();

    int tx = tid % 16;   // n: 4 outputs
    int ty = tid / 16;   // m: 8 batch
    float acc[8][4];
    #pragma unroll
    for (int mm = 0; mm < 8; mm++)
        #pragma unroll
        for (int nn = 0; nn < 4; nn++) acc[mm][nn] = 0.f;

    const float* wbase = g_W2T + loc * 288 * 64;

    for (int k0 = 0; k0 < 288; k0 += BK) {
        // A: 128x8 = 1024 elems, 4 per thread
        #pragma unroll
        for (int kk = 0; kk < BK; kk += 2) {
            int k = k0 + kk + tid / 128;
            int m = tid % 128;
            As[kk + tid / 128][m] = g_h1[rowoff[k] + m0 + m];
        }
        // W: 8x64 = 512 elems, 2 per thread
        #pragma unroll
        for (int kk = 0; kk < BK; kk += 4) {
            int k = k0 + kk + tid / 64;
            int n = tid % 64;
            Ws[kk + tid / 64][n] = wbase[k * 64 + n];
        }
        __syncthreads();
        #pragma unroll
        for (int kk = 0; kk < BK; kk++) {
            float4 a0 = *(const float4*)&As[kk][ty * 8];
            float4 a1 = *(const float4*)&As[kk][ty * 8 + 4];
            float4 w0 = *(const float4*)&Ws[kk][tx * 4];
            float av[8] = {a0.x, a0.y, a0.z, a0.w, a1.x, a1.y, a1.z, a1.w};
            float wv[4] = {w0.x, w0.y, w0.z, w0.w};
            #pragma unroll
            for (int mm = 0; mm < 8; mm++)
                #pragma unroll
                for (int nn = 0; nn < 4; nn++)
                    acc[mm][nn] = fmaf(av[mm], wv[nn], acc[mm][nn]);
        }
        __syncthreads();
    }
    // epilogue: relu(acc + bias) -> h2[(o*36+loc)*B + b], float4 along batch
    #pragma unroll
    for (int nn = 0; nn < 4; nn++) {
        int o = tx * 4 + nn;
        float bias = b2[o * 36 + loc];
        float4 s0, s1;
        s0.x = fmaxf(acc[0][nn] + bias, 0.f);
        s0.y = fmaxf(acc[1][nn] + bias, 0.f);
        s0.z = fmaxf(acc[2][nn] + bias, 0.f);
        s0.w = fmaxf(acc[3][nn] + bias, 0.f);
        s1.x = fmaxf(acc[4][nn] + bias, 0.f);
        s1.y = fmaxf(acc[5][nn] + bias, 0.f);
        s1.z = fmaxf(acc[6][nn] + bias, 0.f);
        s1.w = fmaxf(acc[7][nn] + bias, 0.f);
        float* dst = &g_h2[(o * 36 + loc) * BATCH + m0 + ty * 8];
        *(float4*)dst       = s0;
        *(float4*)(dst + 4) = s1;
    }
}

// ---------------------------------------------------------------------------
// LL3: per-location GEMM. M=8192, N=128, K=576.
// grid = (16, 64). block 256 = 16x16, thread tile 8x8, BK=8.
// ---------------------------------------------------------------------------
__global__ __launch_bounds__(256) void ll3_k(const float* __restrict__ b3) {
    const int BK = 8;
    int loc = blockIdx.x;
    int i = loc / 4, j = loc % 4;
    int m0 = blockIdx.y * 128;

    __shared__ __align__(16) float As[BK][128];
    __shared__ __align__(16) float Ws[BK][128];
    __shared__ int rowoff[576];

    int tid = threadIdx.x;
    for (int k = tid; k < 576; k += 256) {
        int c = k / 9, r = (k % 9) / 3, cc = k % 3;
        rowoff[k] = (c * 36 + (i + r) * 6 + (j + cc)) * BATCH;
    }
    __syncthreads();

    int tx = tid % 16;   // n: 8 outputs
    int ty = tid / 16;   // m: 8 batch
    float acc[8][8];
    #pragma unroll
    for (int mm = 0; mm < 8; mm++)
        #pragma unroll
        for (int nn = 0; nn < 8; nn++) acc[mm][nn] = 0.f;

    const float* wbase = g_W3T + loc * 576 * 128;

    for (int k0 = 0; k0 < 576; k0 += BK) {
        #pragma unroll
        for (int kk = 0; kk < BK; kk += 2) {
            int k = k0 + kk + tid / 128;
            int m = tid % 128;
            As[kk + tid / 128][m] = g_h2[rowoff[k] + m0 + m];
        }
        #pragma unroll
        for (int kk = 0; kk < BK; kk += 2) {
            int k = k0 + kk + tid / 128;
            int n = tid % 128;
            Ws[kk + tid / 128][n] = wbase[k * 128 + n];
        }
        __syncthreads();
        #pragma unroll
        for (int kk = 0; kk < BK; kk++) {
            float4 a0 = *(const float4*)&As[kk][ty * 8];
            float4 a1 = *(const float4*)&As[kk][ty * 8 + 4];
            float4 w0 = *(const float4*)&Ws[kk][tx * 8];
            float4 w1 = *(const float4*)&Ws[kk][tx * 8 + 4];
            float av[8] = {a0.x, a0.y, a0.z, a0.w, a1.x, a1.y, a1.z, a1.w};
            float wv[8] = {w0.x, w0.y, w0.z, w0.w, w1.x, w1.y, w1.z, w1.w};
            #pragma unroll
            for (int mm = 0; mm < 8; mm++)
                #pragma unroll
                for (int nn = 0; nn < 8; nn++)
                    acc[mm][nn] = fmaf(av[mm], wv[nn], acc[mm][nn]);
        }
        __syncthreads();
    }
    // epilogue: f = o*16 + loc (channel-major flatten), relu(acc + bias)
    #pragma unroll
    for (int nn = 0; nn < 8; nn++) {
        int o = tx * 8 + nn;
        float bias = b3[o * 16 + loc];
        float4 s0, s1;
        s0.x = fmaxf(acc[0][nn] + bias, 0.f);
        s0.y = fmaxf(acc[1][nn] + bias, 0.f);
        s0.z = fmaxf(acc[2][nn] + bias, 0.f);
        s0.w = fmaxf(acc[3][nn] + bias, 0.f);
        s1.x = fmaxf(acc[4][nn] + bias, 0.f);
        s1.y = fmaxf(acc[5][nn] + bias, 0.f);
        s1.z = fmaxf(acc[6][nn] + bias, 0.f);
        s1.w = fmaxf(acc[7][nn] + bias, 0.f);
        float* dst = &g_h3[(o * 16 + loc) * BATCH + m0 + ty * 8];
        *(float4*)dst       = s0;
        *(float4*)(dst + 4) = s1;
    }
}

// ---------------------------------------------------------------------------
// Linear head: (B,2048) @ (2048,10)^T + bias, relu.
// grid = B/32. 256 threads: 32 batch x 8 split-K groups; smem reduction.
// ---------------------------------------------------------------------------
__global__ __launch_bounds__(256) void lin_k(const float* __restrict__ Wl,
                                             const float* __restrict__ blin,
                                             float* __restrict__ out) {
    const int CHUNK = 512;                     // f per smem chunk
    __shared__ float Wls[CHUNK * 10];          // 20 KB
    __shared__ float sacc[8][32][10];          // 10 KB

    int m0  = blockIdx.x * 32;
    int tid = threadIdx.x;
    int bl_ = tid % 32;                        // batch within block
    int g   = tid / 32;                        // split-K group (== warp id)

    float acc[10];
    #pragma unroll
    for (int t = 0; t < 10; t++) acc[t] = 0.f;

    for (int c = 0; c < 4; c++) {
        __syncthreads();
        for (int idx = tid; idx < CHUNK * 10; idx += 256) {
            int fl = idx / 10, t = idx % 10;
            Wls[idx] = Wl[t * 2048 + c * CHUNK + fl];
        }
        __syncthreads();
        int fbase = g * (CHUNK / 8);           // 64 f per group per chunk
        #pragma unroll 4
        for (int fl = fbase; fl < fbase + CHUNK / 8; fl++) {
            int f = c * CHUNK + fl;
            float v = g_h3[f * BATCH + m0 + bl_];
            const float* w = &Wls[fl * 10];
            #pragma unroll
            for (int t = 0; t < 10; t++) acc[t] = fmaf(v, w[t], acc[t]);
        }
    }
    #pragma unroll
    for (int t = 0; t < 10; t++) sacc[g][bl_][t] = acc[t];
    __syncthreads();
    // 320 (batch, class) pairs per block; blockDim = 256, so stride the loop.
    for (int t2 = tid; t2 < 320; t2 += 256) {
        int bb = t2 / 10, t = t2 % 10;
        float s = blin[t];
        #pragma unroll
        for (int gg = 0; gg < 8; gg++) s += sacc[gg][bb][t];
        out[(m0 + bb) * 10 + t] = fmaxf(s, 0.f);
    }
}

// ---------------------------------------------------------------------------
extern "C" void kernel_launch(void* const* d_in, const int* in_sizes, int n_in,
                              void* d_out, int out_size) {
    const float* x  = (const float*)d_in[0];
    const float* W1 = (const float*)d_in[1];
    const float* b1 = (const float*)d_in[2];
    const float* W2 = (const float*)d_in[3];
    const float* b2 = (const float*)d_in[4];
    const float* W3 = (const float*)d_in[5];
    const float* b3 = (const float*)d_in[6];
    const float* Wl = (const float*)d_in[7];
    const float* bl = (const float*)d_in[8];
    float* out = (float*)d_out;

    transpose_x_k<<<dim3(25, 256), dim3(32, 8)>>>(x);
    wtrans2_k<<<(64 * 288 * 36 + 255) / 256, 256>>>(W2);
    wtrans3_k<<<(128 * 576 * 16 + 255) / 256, 256>>>(W3);
    ll1_k<<<dim3(169, 32), 256>>>(W1, b1);
    ll2_k<<<dim3(36, 64), 256>>>(b2);
    ll3_k<<<dim3(16, 64), 256>>>(b3);
    lin_k<<<256, 256>>>(Wl, bl, out);
}

// round 10
// speedup vs baseline: 1.1335x; 1.1310x over previous
#include <cuda_runtime.h>
#include <cuda_bf16.h>
#include <cstdint>

// ---------------------------------------------------------------------------
// FreeConvNetwork, B=8192. Hybrid bisect build:
//   - Everything identical to the PASSING R3 kernel (fp32 SGEMM ll2, fp32
//     activations, fp32 ll1/lin/transpose)  [all exonerated at mem-delta 0]
//   - ONE new kernel: LL3 on mma.sync bf16 hi/lo split tensor cores.
// If the 384MiB local-pool violation reappears, the mma.sync kernel is the
// proven trigger; if it passes, LL3 drops ~830us -> ~150us.
// ---------------------------------------------------------------------------

#define BATCH 8192

__device__ float    g_xT [784        * BATCH];   // (28*28, B)
__device__ float    g_h1 [32  * 169  * BATCH];   // (c*169 + i*13+j, B)
__device__ float    g_h2 [64  * 36   * BATCH];   // (c*36  + i*6 +j, B)
__device__ float    g_h3 [2048       * BATCH];   // (c*16  + i*4 +j, B)
__device__ float    g_W2T[36 * 288 * 64];        // (loc, k, o)
__device__ unsigned g_W3p[16 * 128 * 576];       // (loc, o, k) packed bf16 pairs

__device__ __forceinline__ unsigned pack_pair(float v) {
    __nv_bfloat16 h = __float2bfloat16(v);
    float r = v - __bfloat162float(h);
    __nv_bfloat16 l = __float2bfloat16(r);
    return ((unsigned)__bfloat16_as_ushort(l) << 16) | (unsigned)__bfloat16_as_ushort(h);
}

#define MMA(c, a0, a1, a2, a3, b) \
    asm volatile( \
        "mma.sync.aligned.m16n8k16.row.col.f32.bf16.bf16.f32 " \
        "{%0,%1,%2,%3}, {%4,%5,%6,%7}, {%8,%9}, {%0,%1,%2,%3};" \
        : "+f"(c.x), "+f"(c.y), "+f"(c.z), "+f"(c.w) \
        : "r"(a0), "r"(a1), "r"(a2), "r"(a3), "r"(b.x), "r"(b.y))

#define PERM_HI(x, y) __byte_perm(x, y, 0x5410)
#define PERM_LO(x, y) __byte_perm(x, y, 0x7632)

// ---------------------------------------------------------------------------
// x (B,784) -> xT (784,B)   [R3 verbatim]
// ---------------------------------------------------------------------------
__global__ void transpose_x_k(const float* __restrict__ x) {
    __shared__ float tile[32][33];
    int c  = blockIdx.x * 32 + threadIdx.x;
    int r0 = blockIdx.y * 32;
    #pragma unroll
    for (int i = threadIdx.y; i < 32; i += 8) {
        int r = r0 + i;
        tile[i][threadIdx.x] = (c < 784) ? x[r * 784 + c] : 0.f;
    }
    __syncthreads();
    int oc  = r0 + threadIdx.x;
    int or0 = blockIdx.x * 32;
    #pragma unroll
    for (int i = threadIdx.y; i < 32; i += 8) {
        int orow = or0 + i;
        if (orow < 784) g_xT[orow * BATCH + oc] = tile[threadIdx.x][i];
    }
}

// ---------------------------------------------------------------------------
// W2 (O,K2,L) -> W2T (L,K2,O)   [R3 verbatim]
// ---------------------------------------------------------------------------
__global__ void wtrans2_k(const float* __restrict__ W) {
    const int O = 64, K2 = 288, L = 36;
    int idx = blockIdx.x * blockDim.x + threadIdx.x;
    if (idx >= O * K2 * L) return;
    int o = idx % O; int k = (idx / O) % K2; int l = idx / (O * K2);
    g_W2T[idx] = W[(o * K2 + k) * L + l];
}

// W3 (128,576,16) fp32 -> (loc, o, k) packed pairs
__global__ void wpack3_k(const float* __restrict__ W) {
    int idx = blockIdx.x * 256 + threadIdx.x;
    if (idx >= 16 * 128 * 576) return;
    int k   = idx % 576;
    int o   = (idx / 576) % 128;
    int loc = idx / (576 * 128);
    g_W3p[idx] = pack_pair(W[(o * 576 + k) * 16 + loc]);
}

// ---------------------------------------------------------------------------
// LL1   [R3 verbatim]
// ---------------------------------------------------------------------------
__global__ __launch_bounds__(256) void ll1_k(const float* __restrict__ W1,
                                             const float* __restrict__ b1) {
    int loc = blockIdx.x;
    int i = loc / 13, j = loc % 13;
    int b = blockIdx.y * 256 + threadIdx.x;

    __shared__ float ws[32 * 9];
    __shared__ float bs[32];
    for (int t = threadIdx.x; t < 32 * 9; t += 256) {
        int o = t / 9, k = t % 9;
        ws[t] = W1[(o * 9 + k) * 169 + loc];
    }
    if (threadIdx.x < 32) bs[threadIdx.x] = b1[threadIdx.x * 169 + loc];
    __syncthreads();

    float v[9];
    #pragma unroll
    for (int k = 0; k < 9; k++) {
        int di = k / 3, dj = k % 3;
        v[k] = g_xT[((2 * i + di) * 28 + (2 * j + dj)) * BATCH + b];
    }
    #pragma unroll
    for (int o = 0; o < 32; o++) {
        float acc = bs[o];
        #pragma unroll
        for (int k = 0; k < 9; k++) acc = fmaf(ws[o * 9 + k], v[k], acc);
        g_h1[(o * 169 + loc) * BATCH + b] = fmaxf(acc, 0.f);
    }
}

// ---------------------------------------------------------------------------
// LL2 SGEMM   [R3 verbatim]
// ---------------------------------------------------------------------------
__global__ __launch_bounds__(256) void ll2_k(const float* __restrict__ b2) {
    const int BK = 8;
    int loc = blockIdx.x;
    int i = loc / 6, j = loc % 6;
    int m0 = blockIdx.y * 128;

    __shared__ __align__(16) float As[BK][128];
    __shared__ __align__(16) float Ws[BK][64];
    __shared__ int rowoff[288];

    int tid = threadIdx.x;
    for (int k = tid; k < 288; k += 256) {
        int c = k / 9, r = (k % 9) / 3, cc = k % 3;
        rowoff[k] = (c * 169 + (2 * i + r) * 13 + (2 * j + cc)) * BATCH;
    }
    __syncthreads();

    int tx = tid % 16;
    int ty = tid / 16;
    float acc[8][4];
    #pragma unroll
    for (int mm = 0; mm < 8; mm++)
        #pragma unroll
        for (int nn = 0; nn < 4; nn++) acc[mm][nn] = 0.f;

    const float* wbase = g_W2T + loc * 288 * 64;

    for (int k0 = 0; k0 < 288; k0 += BK) {
        #pragma unroll
        for (int kk = 0; kk < BK; kk += 2) {
            int k = k0 + kk + tid / 128;
            int m = tid % 128;
            As[kk + tid / 128][m] = g_h1[rowoff[k] + m0 + m];
        }
        #pragma unroll
        for (int kk = 0; kk < BK; kk += 4) {
            int k = k0 + kk + tid / 64;
            int n = tid % 64;
            Ws[kk + tid / 64][n] = wbase[k * 64 + n];
        }
        __syncthreads();
        #pragma unroll
        for (int kk = 0; kk < BK; kk++) {
            float4 a0 = *(const float4*)&As[kk][ty * 8];
            float4 a1 = *(const float4*)&As[kk][ty * 8 + 4];
            float4 w0 = *(const float4*)&Ws[kk][tx * 4];
            float av[8] = {a0.x, a0.y, a0.z, a0.w, a1.x, a1.y, a1.z, a1.w};
            float wv[4] = {w0.x, w0.y, w0.z, w0.w};
            #pragma unroll
            for (int mm = 0; mm < 8; mm++)
                #pragma unroll
                for (int nn = 0; nn < 4; nn++)
                    acc[mm][nn] = fmaf(av[mm], wv[nn], acc[mm][nn]);
        }
        __syncthreads();
    }
    #pragma unroll
    for (int nn = 0; nn < 4; nn++) {
        int o = tx * 4 + nn;
        float bias = b2[o * 36 + loc];
        float4 s0, s1;
        s0.x = fmaxf(acc[0][nn] + bias, 0.f);
        s0.y = fmaxf(acc[1][nn] + bias, 0.f);
        s0.z = fmaxf(acc[2][nn] + bias, 0.f);
        s0.w = fmaxf(acc[3][nn] + bias, 0.f);
        s1.x = fmaxf(acc[4][nn] + bias, 0.f);
        s1.y = fmaxf(acc[5][nn] + bias, 0.f);
        s1.z = fmaxf(acc[6][nn] + bias, 0.f);
        s1.w = fmaxf(acc[7][nn] + bias, 0.f);
        float* dst = &g_h2[(o * 36 + loc) * BATCH + m0 + ty * 8];
        *(float4*)dst       = s0;
        *(float4*)(dst + 4) = s1;
    }
}

// ---------------------------------------------------------------------------
// LL3 on mma.sync (the ONE new kernel). N=128, K=576, 16 locs.
// CTA = (loc, 128-batch, 64-n block); 256 thr = 8 warps (4m x 2n);
// warp tile 32m x 32n; BK=32; fully scalarized fragments.
// A: fp32 g_h2 -> hi/lo packed u32 in regs during smem fill.
// Out: fp32 g_h3 (lin_k unchanged).
// ---------------------------------------------------------------------------
#define LOADB3(NIv, bh, bl) do { \
    int _n = wn * 32 + (NIv) * 8 + (lane >> 2); \
    int _k = kb + (lane & 3) * 2; \
    uint2 _q0 = *(const uint2*)&Bs[_n][_k]; \
    uint2 _q1 = *(const uint2*)&Bs[_n][_k + 8]; \
    bh.x = PERM_HI(_q0.x, _q0.y); bh.y = PERM_HI(_q1.x, _q1.y); \
    bl.x = PERM_LO(_q0.x, _q0.y); bl.y = PERM_LO(_q1.x, _q1.y); \
} while (0)

#define MIBLOCK3(MI, c0, c1, c2, c3) do { \
    int _m = wm * 32 + (MI) * 16 + (lane >> 2); \
    int _k = kb + (lane & 3) * 2; \
    uint2 _p0 = *(const uint2*)&As[_m][_k]; \
    uint2 _p1 = *(const uint2*)&As[_m + 8][_k]; \
    uint2 _p2 = *(const uint2*)&As[_m][_k + 8]; \
    uint2 _p3 = *(const uint2*)&As[_m + 8][_k + 8]; \
    unsigned ah0 = PERM_HI(_p0.x, _p0.y), ah1 = PERM_HI(_p1.x, _p1.y); \
    unsigned ah2 = PERM_HI(_p2.x, _p2.y), ah3 = PERM_HI(_p3.x, _p3.y); \
    unsigned al0 = PERM_LO(_p0.x, _p0.y), al1 = PERM_LO(_p1.x, _p1.y); \
    unsigned al2 = PERM_LO(_p2.x, _p2.y), al3 = PERM_LO(_p3.x, _p3.y); \
    MMA(c0, ah0, ah1, ah2, ah3, bh0); \
    MMA(c0, ah0, ah1, ah2, ah3, bl0); \
    MMA(c0, al0, al1, al2, al3, bh0); \
    MMA(c1, ah0, ah1, ah2, ah3, bh1); \
    MMA(c1, ah0, ah1, ah2, ah3, bl1); \
    MMA(c1, al0, al1, al2, al3, bh1); \
    MMA(c2, ah0, ah1, ah2, ah3, bh2); \
    MMA(c2, ah0, ah1, ah2, ah3, bl2); \
    MMA(c2, al0, al1, al2, al3, bh2); \
    MMA(c3, ah0, ah1, ah2, ah3, bh3); \
    MMA(c3, ah0, ah1, ah2, ah3, bl3); \
    MMA(c3, al0, al1, al2, al3, bh3); \
} while (0)

#define EPI3(MI, NIv, c) do { \
    int _m = m0 + wm * 32 + (MI) * 16 + (lane >> 2); \
    int _ol = wn * 32 + (NIv) * 8 + (lane & 3) * 2; \
    int _o  = n0 + _ol; \
    float _b0 = biasS[_ol], _b1 = biasS[_ol + 1]; \
    size_t _ba0 = (size_t)(_o * 16 + loc) * BATCH; \
    size_t _ba1 = (size_t)((_o + 1) * 16 + loc) * BATCH; \
    g_h3[_ba0 + _m]     = fmaxf(c.x + _b0, 0.f); \
    g_h3[_ba1 + _m]     = fmaxf(c.y + _b1, 0.f); \
    g_h3[_ba0 + _m + 8] = fmaxf(c.z + _b0, 0.f); \
    g_h3[_ba1 + _m + 8] = fmaxf(c.w + _b1, 0.f); \
} while (0)

__global__ __launch_bounds__(256, 1) void ll3_hmma_k(const float* __restrict__ b3) {
    constexpr int SA = 34;
    __shared__ unsigned As[128][SA];   // [m][k] packed pairs
    __shared__ unsigned Bs[64][SA];    // [n][k] packed pairs
    __shared__ int   rowoffS[576];
    __shared__ float biasS[64];

    int tid  = threadIdx.x;
    int lane = tid & 31;
    int wid  = tid >> 5;
    int wn   = wid & 1;
    int wm   = wid >> 1;
    int loc  = blockIdx.x;
    int m0   = blockIdx.y * 128;
    int n0   = blockIdx.z * 64;
    int li = loc / 4, lj = loc % 4;

    for (int k = tid; k < 576; k += 256) {
        int c = k / 9, r = (k % 9) / 3, cc = k % 3;
        rowoffS[k] = (c * 36 + (li + r) * 6 + (lj + cc)) * BATCH;
    }
    if (tid < 64) biasS[tid] = b3[(n0 + tid) * 16 + loc];

    float4 c00 = {0,0,0,0}, c01 = {0,0,0,0}, c02 = {0,0,0,0}, c03 = {0,0,0,0};
    float4 c10 = {0,0,0,0}, c11 = {0,0,0,0}, c12 = {0,0,0,0}, c13 = {0,0,0,0};

    const unsigned* wloc = g_W3p + (size_t)loc * 128 * 576 + (size_t)n0 * 576;

    for (int k0 = 0; k0 < 576; k0 += 32) {
        __syncthreads();
        // A tile: 128m x 32k; load fp32, split+pack in regs, store u32.
        #pragma unroll
        for (int p = 0; p < 4; p++) {
            int k  = p * 8 + wid;
            int m4 = lane * 4;
            float4 v = *(const float4*)(g_h2 + rowoffS[k0 + k] + m0 + m4);
            As[m4 + 0][k] = pack_pair(v.x);
            As[m4 + 1][k] = pack_pair(v.y);
            As[m4 + 2][k] = pack_pair(v.z);
            As[m4 + 3][k] = pack_pair(v.w);
        }
        // B tile: 64n x 32k, coalesced along k.
        #pragma unroll
        for (int p = 0; p < 8; p++) {
            int idx = p * 256 + tid;
            int k = idx & 31, n = idx >> 5;
            Bs[n][k] = wloc[n * 576 + k0 + k];
        }
        __syncthreads();

        {
            int kb = 0;
            uint2 bh0, bl0, bh1, bl1, bh2, bl2, bh3, bl3;
            LOADB3(0, bh0, bl0); LOADB3(1, bh1, bl1);
            LOADB3(2, bh2, bl2); LOADB3(3, bh3, bl3);
            MIBLOCK3(0, c00, c01, c02, c03);
            MIBLOCK3(1, c10, c11, c12, c13);
        }
        {
            int kb = 16;
            uint2 bh0, bl0, bh1, bl1, bh2, bl2, bh3, bl3;
            LOADB3(0, bh0, bl0); LOADB3(1, bh1, bl1);
            LOADB3(2, bh2, bl2); LOADB3(3, bh3, bl3);
            MIBLOCK3(0, c00, c01, c02, c03);
            MIBLOCK3(1, c10, c11, c12, c13);
        }
    }

    EPI3(0, 0, c00); EPI3(0, 1, c01); EPI3(0, 2, c02); EPI3(0, 3, c03);
    EPI3(1, 0, c10); EPI3(1, 1, c11); EPI3(1, 2, c12); EPI3(1, 3, c13);
}

// ---------------------------------------------------------------------------
// Linear head   [R3 verbatim]
// ---------------------------------------------------------------------------
__global__ __launch_bounds__(256) void lin_k(const float* __restrict__ Wl,
                                             const float* __restrict__ blin,
                                             float* __restrict__ out) {
    const int CHUNK = 512;
    __shared__ float Wls[CHUNK * 10];
    __shared__ float sacc[8][32][10];

    int m0  = blockIdx.x * 32;
    int tid = threadIdx.x;
    int bl_ = tid % 32;
    int g   = tid / 32;

    float acc[10];
    #pragma unroll
    for (int t = 0; t < 10; t++) acc[t] = 0.f;

    for (int c = 0; c < 4; c++) {
        __syncthreads();
        for (int idx = tid; idx < CHUNK * 10; idx += 256) {
            int fl = idx / 10, t = idx % 10;
            Wls[idx] = Wl[t * 2048 + c * CHUNK + fl];
        }
        __syncthreads();
        int fbase = g * (CHUNK / 8);
        #pragma unroll 4
        for (int fl = fbase; fl < fbase + CHUNK / 8; fl++) {
            int f = c * CHUNK + fl;
            float v = g_h3[f * BATCH + m0 + bl_];
            const float* w = &Wls[fl * 10];
            #pragma unroll
            for (int t = 0; t < 10; t++) acc[t] = fmaf(v, w[t], acc[t]);
        }
    }
    #pragma unroll
    for (int t = 0; t < 10; t++) sacc[g][bl_][t] = acc[t];
    __syncthreads();
    for (int t2 = tid; t2 < 320; t2 += 256) {
        int bb = t2 / 10, t = t2 % 10;
        float s = blin[t];
        #pragma unroll
        for (int gg = 0; gg < 8; gg++) s += sacc[gg][bb][t];
        out[(m0 + bb) * 10 + t] = fmaxf(s, 0.f);
    }
}

// ---------------------------------------------------------------------------
extern "C" void kernel_launch(void* const* d_in, const int* in_sizes, int n_in,
                              void* d_out, int out_size) {
    const float* x  = (const float*)d_in[0];
    const float* W1 = (const float*)d_in[1];
    const float* b1 = (const float*)d_in[2];
    const float* W2 = (const float*)d_in[3];
    const float* b2 = (const float*)d_in[4];
    const float* W3 = (const float*)d_in[5];
    const float* b3 = (const float*)d_in[6];
    const float* Wl = (const float*)d_in[7];
    const float* bl = (const float*)d_in[8];
    float* out = (float*)d_out;

    transpose_x_k<<<dim3(25, 256), dim3(32, 8)>>>(x);
    wtrans2_k<<<(64 * 288 * 36 + 255) / 256, 256>>>(W2);
    wpack3_k<<<(16 * 128 * 576 + 255) / 256, 256>>>(W3);
    ll1_k<<<dim3(169, 32), 256>>>(W1, b1);
    ll2_k<<<dim3(36, 64), 256>>>(b2);
    ll3_hmma_k<<<dim3(16, 64, 2), 256>>>(b3);
    lin_k<<<256, 256>>>(Wl, bl, out);
}

// round 12
// speedup vs baseline: 1.3343x; 1.1772x over previous
#include <cuda_runtime.h>
#include <cuda_bf16.h>
#include <cstdint>

// ---------------------------------------------------------------------------
// FreeConvNetwork, B=8192. LL2 + LL3 on mma.sync bf16 hi/lo-split tensor
// cores (fp32 accumulate). ALL patterns proven clean in R10:
//   - pack_pair ONLY in A-fill (registers) and standalone prep kernels
//   - hmma epilogues write fp32 ONLY (packed-output epilogues reproducibly
//     trigger a 384MiB local-memory pool -> harness violation; R6-R9, R11)
// value = hi + lo (bf16 each); D = Ahi*Bhi + Ahi*Blo + Alo*Bhi.
// Activations feature-major, batch-innermost. Patch index k = c*9 + di*3 + dj.
// ---------------------------------------------------------------------------

#define BATCH 8192

__device__ float    g_xT [784        * BATCH];   // (28*28, B)
__device__ float    g_h1 [32  * 169  * BATCH];   // fp32
__device__ float    g_h2 [64  * 36   * BATCH];   // fp32
__device__ float    g_h3 [2048       * BATCH];   // fp32
__device__ unsigned g_W2p[36 * 64  * 288];       // (loc, o, k) packed pairs
__device__ unsigned g_W3p[16 * 128 * 576];       // (loc, o, k) packed pairs

__device__ __forceinline__ unsigned pack_pair(float v) {
    __nv_bfloat16 h = __float2bfloat16(v);
    float r = v - __bfloat162float(h);
    __nv_bfloat16 l = __float2bfloat16(r);
    return ((unsigned)__bfloat16_as_ushort(l) << 16) | (unsigned)__bfloat16_as_ushort(h);
}

#define MMA(c, a0, a1, a2, a3, b) \
    asm volatile( \
        "mma.sync.aligned.m16n8k16.row.col.f32.bf16.bf16.f32 " \
        "{%0,%1,%2,%3}, {%4,%5,%6,%7}, {%8,%9}, {%0,%1,%2,%3};" \
        : "+f"(c.x), "+f"(c.y), "+f"(c.z), "+f"(c.w) \
        : "r"(a0), "r"(a1), "r"(a2), "r"(a3), "r"(b.x), "r"(b.y))

#define PERM_HI(x, y) __byte_perm(x, y, 0x5410)
#define PERM_LO(x, y) __byte_perm(x, y, 0x7632)

// ---------------------------------------------------------------------------
// x (B,784) -> xT (784,B)   [proven]
// ---------------------------------------------------------------------------
__global__ void transpose_x_k(const float* __restrict__ x) {
    __shared__ float tile[32][33];
    int c  = blockIdx.x * 32 + threadIdx.x;
    int r0 = blockIdx.y * 32;
    #pragma unroll
    for (int i = threadIdx.y; i < 32; i += 8) {
        int r = r0 + i;
        tile[i][threadIdx.x] = (c < 784) ? x[r * 784 + c] : 0.f;
    }
    __syncthreads();
    int oc  = r0 + threadIdx.x;
    int or0 = blockIdx.x * 32;
    #pragma unroll
    for (int i = threadIdx.y; i < 32; i += 8) {
        int orow = or0 + i;
        if (orow < 784) g_xT[orow * BATCH + oc] = tile[threadIdx.x][i];
    }
}

// ---------------------------------------------------------------------------
// Weight prep (concrete kernels, proven body)
// ---------------------------------------------------------------------------
__global__ void wpack2_k(const float* __restrict__ W) {
    int idx = blockIdx.x * 256 + threadIdx.x;
    if (idx >= 36 * 64 * 288) return;
    int k   = idx % 288;
    int o   = (idx / 288) % 64;
    int loc = idx / (288 * 64);
    g_W2p[idx] = pack_pair(W[(o * 288 + k) * 36 + loc]);
}
__global__ void wpack3_k(const float* __restrict__ W) {
    int idx = blockIdx.x * 256 + threadIdx.x;
    if (idx >= 16 * 128 * 576) return;
    int k   = idx % 576;
    int o   = (idx / 576) % 128;
    int loc = idx / (576 * 128);
    g_W3p[idx] = pack_pair(W[(o * 576 + k) * 16 + loc]);
}

// ---------------------------------------------------------------------------
// LL1 (CUDA core, K=9), fp32 out.   [proven]
// ---------------------------------------------------------------------------
__global__ __launch_bounds__(256) void ll1_k(const float* __restrict__ W1,
                                             const float* __restrict__ b1) {
    int loc = blockIdx.x;
    int i = loc / 13, j = loc % 13;
    int b = blockIdx.y * 256 + threadIdx.x;

    __shared__ float ws[32 * 9];
    __shared__ float bs[32];
    for (int t = threadIdx.x; t < 32 * 9; t += 256) {
        int o = t / 9, k = t % 9;
        ws[t] = W1[(o * 9 + k) * 169 + loc];
    }
    if (threadIdx.x < 32) bs[threadIdx.x] = b1[threadIdx.x * 169 + loc];
    __syncthreads();

    float v[9];
    #pragma unroll
    for (int k = 0; k < 9; k++) {
        int di = k / 3, dj = k % 3;
        v[k] = g_xT[((2 * i + di) * 28 + (2 * j + dj)) * BATCH + b];
    }
    #pragma unroll
    for (int o = 0; o < 32; o++) {
        float acc = bs[o];
        #pragma unroll
        for (int k = 0; k < 9; k++) acc = fmaf(ws[o * 9 + k], v[k], acc);
        g_h1[(o * 169 + loc) * BATCH + b] = fmaxf(acc, 0.f);
    }
}

// ---------------------------------------------------------------------------
// Shared hmma fragment macros (proven R10 body).
// ---------------------------------------------------------------------------
#define LOADB_(Bs, NIv, bh, bl) do { \
    int _n = wn * 32 + (NIv) * 8 + (lane >> 2); \
    int _k = kb + (lane & 3) * 2; \
    uint2 _q0 = *(const uint2*)&Bs[_n][_k]; \
    uint2 _q1 = *(const uint2*)&Bs[_n][_k + 8]; \
    bh.x = PERM_HI(_q0.x, _q0.y); bh.y = PERM_HI(_q1.x, _q1.y); \
    bl.x = PERM_LO(_q0.x, _q0.y); bl.y = PERM_LO(_q1.x, _q1.y); \
} while (0)

#define MIBLOCK_(As, MI, c0, c1, c2, c3) do { \
    int _m = wm * 32 + (MI) * 16 + (lane >> 2); \
    int _k = kb + (lane & 3) * 2; \
    uint2 _p0 = *(const uint2*)&As[_m][_k]; \
    uint2 _p1 = *(const uint2*)&As[_m + 8][_k]; \
    uint2 _p2 = *(const uint2*)&As[_m][_k + 8]; \
    uint2 _p3 = *(const uint2*)&As[_m + 8][_k + 8]; \
    unsigned ah0 = PERM_HI(_p0.x, _p0.y), ah1 = PERM_HI(_p1.x, _p1.y); \
    unsigned ah2 = PERM_HI(_p2.x, _p2.y), ah3 = PERM_HI(_p3.x, _p3.y); \
    unsigned al0 = PERM_LO(_p0.x, _p0.y), al1 = PERM_LO(_p1.x, _p1.y); \
    unsigned al2 = PERM_LO(_p2.x, _p2.y), al3 = PERM_LO(_p3.x, _p3.y); \
    MMA(c0, ah0, ah1, ah2, ah3, bh0); \
    MMA(c0, ah0, ah1, ah2, ah3, bl0); \
    MMA(c0, al0, al1, al2, al3, bh0); \
    MMA(c1, ah0, ah1, ah2, ah3, bh1); \
    MMA(c1, ah0, ah1, ah2, ah3, bl1); \
    MMA(c1, al0, al1, al2, al3, bh1); \
    MMA(c2, ah0, ah1, ah2, ah3, bh2); \
    MMA(c2, ah0, ah1, ah2, ah3, bl2); \
    MMA(c2, al0, al1, al2, al3, bh2); \
    MMA(c3, ah0, ah1, ah2, ah3, bh3); \
    MMA(c3, ah0, ah1, ah2, ah3, bl3); \
    MMA(c3, al0, al1, al2, al3, bh3); \
} while (0)

// fp32 epilogue ONLY (packed epilogues trigger the lmem-pool violation).
#define EPIF_(dst, LOCS, MI, NIv, c) do { \
    int _m = m0 + wm * 32 + (MI) * 16 + (lane >> 2); \
    int _ol = wn * 32 + (NIv) * 8 + (lane & 3) * 2; \
    int _o  = n0 + _ol; \
    float _b0 = biasS[_ol], _b1 = biasS[_ol + 1]; \
    size_t _ba0 = (size_t)(_o * (LOCS) + loc) * BATCH; \
    size_t _ba1 = (size_t)((_o + 1) * (LOCS) + loc) * BATCH; \
    dst[_ba0 + _m]     = fmaxf(c.x + _b0, 0.f); \
    dst[_ba1 + _m]     = fmaxf(c.y + _b1, 0.f); \
    dst[_ba0 + _m + 8] = fmaxf(c.z + _b0, 0.f); \
    dst[_ba1 + _m + 8] = fmaxf(c.w + _b1, 0.f); \
} while (0)

// ---------------------------------------------------------------------------
// LL2 on mma.sync. N=64, K=288, 36 locs. CTA = (loc, 128-batch); 256 thr =
// 8 warps (4m x 2n); warp tile 32x32; BK=32 (9 chunks). A: fp32 g_h1,
// pack_pair in regs during fill [proven]. Out: fp32 g_h2 [proven].
// ---------------------------------------------------------------------------
__global__ __launch_bounds__(256, 1) void ll2_hmma_k(const float* __restrict__ b2) {
    constexpr int SA = 34;
    __shared__ unsigned As[128][SA];
    __shared__ unsigned Bs[64][SA];
    __shared__ int   rowoffS[288];
    __shared__ float biasS[64];

    int tid  = threadIdx.x;
    int lane = tid & 31;
    int wid  = tid >> 5;
    int wn   = wid & 1;
    int wm   = wid >> 1;
    int loc  = blockIdx.x;
    int m0   = blockIdx.y * 128;
    const int n0 = 0;
    int li = loc / 6, lj = loc % 6;

    for (int k = tid; k < 288; k += 256) {
        int c = k / 9, r = (k % 9) / 3, cc = k % 3;
        rowoffS[k] = (c * 169 + (2 * li + r) * 13 + (2 * lj + cc)) * BATCH;
    }
    if (tid < 64) biasS[tid] = b2[tid * 36 + loc];

    float4 c00 = {0,0,0,0}, c01 = {0,0,0,0}, c02 = {0,0,0,0}, c03 = {0,0,0,0};
    float4 c10 = {0,0,0,0}, c11 = {0,0,0,0}, c12 = {0,0,0,0}, c13 = {0,0,0,0};

    const unsigned* wloc = g_W2p + (size_t)loc * 64 * 288;

    for (int k0 = 0; k0 < 288; k0 += 32) {
        __syncthreads();
        #pragma unroll
        for (int p = 0; p < 4; p++) {
            int k  = p * 8 + wid;
            int m4 = lane * 4;
            float4 v = *(const float4*)(g_h1 + rowoffS[k0 + k] + m0 + m4);
            As[m4 + 0][k] = pack_pair(v.x);
            As[m4 + 1][k] = pack_pair(v.y);
            As[m4 + 2][k] = pack_pair(v.z);
            As[m4 + 3][k] = pack_pair(v.w);
        }
        #pragma unroll
        for (int p = 0; p < 8; p++) {
            int idx = p * 256 + tid;
            int k = idx & 31, n = idx >> 5;
            Bs[n][k] = wloc[n * 288 + k0 + k];
        }
        __syncthreads();

        {
            int kb = 0;
            uint2 bh0, bl0, bh1, bl1, bh2, bl2, bh3, bl3;
            LOADB_(Bs, 0, bh0, bl0); LOADB_(Bs, 1, bh1, bl1);
            LOADB_(Bs, 2, bh2, bl2); LOADB_(Bs, 3, bh3, bl3);
            MIBLOCK_(As, 0, c00, c01, c02, c03);
            MIBLOCK_(As, 1, c10, c11, c12, c13);
        }
        {
            int kb = 16;
            uint2 bh0, bl0, bh1, bl1, bh2, bl2, bh3, bl3;
            LOADB_(Bs, 0, bh0, bl0); LOADB_(Bs, 1, bh1, bl1);
            LOADB_(Bs, 2, bh2, bl2); LOADB_(Bs, 3, bh3, bl3);
            MIBLOCK_(As, 0, c00, c01, c02, c03);
            MIBLOCK_(As, 1, c10, c11, c12, c13);
        }
    }

    EPIF_(g_h2, 36, 0, 0, c00); EPIF_(g_h2, 36, 0, 1, c01);
    EPIF_(g_h2, 36, 0, 2, c02); EPIF_(g_h2, 36, 0, 3, c03);
    EPIF_(g_h2, 36, 1, 0, c10); EPIF_(g_h2, 36, 1, 1, c11);
    EPIF_(g_h2, 36, 1, 2, c12); EPIF_(g_h2, 36, 1, 3, c13);
}

// ---------------------------------------------------------------------------
// LL3 on mma.sync — R10 kernel verbatim. N=128, K=576, 16 locs.
// ---------------------------------------------------------------------------
__global__ __launch_bounds__(256, 1) void ll3_hmma_k(const float* __restrict__ b3) {
    constexpr int SA = 34;
    __shared__ unsigned As[128][SA];
    __shared__ unsigned Bs[64][SA];
    __shared__ int   rowoffS[576];
    __shared__ float biasS[64];

    int tid  = threadIdx.x;
    int lane = tid & 31;
    int wid  = tid >> 5;
    int wn   = wid & 1;
    int wm   = wid >> 1;
    int loc  = blockIdx.x;
    int m0   = blockIdx.y * 128;
    int n0   = blockIdx.z * 64;
    int li = loc / 4, lj = loc % 4;

    for (int k = tid; k < 576; k += 256) {
        int c = k / 9, r = (k % 9) / 3, cc = k % 3;
        rowoffS[k] = (c * 36 + (li + r) * 6 + (lj + cc)) * BATCH;
    }
    if (tid < 64) biasS[tid] = b3[(n0 + tid) * 16 + loc];

    float4 c00 = {0,0,0,0}, c01 = {0,0,0,0}, c02 = {0,0,0,0}, c03 = {0,0,0,0};
    float4 c10 = {0,0,0,0}, c11 = {0,0,0,0}, c12 = {0,0,0,0}, c13 = {0,0,0,0};

    const unsigned* wloc = g_W3p + (size_t)loc * 128 * 576 + (size_t)n0 * 576;

    for (int k0 = 0; k0 < 576; k0 += 32) {
        __syncthreads();
        #pragma unroll
        for (int p = 0; p < 4; p++) {
            int k  = p * 8 + wid;
            int m4 = lane * 4;
            float4 v = *(const float4*)(g_h2 + rowoffS[k0 + k] + m0 + m4);
            As[m4 + 0][k] = pack_pair(v.x);
            As[m4 + 1][k] = pack_pair(v.y);
            As[m4 + 2][k] = pack_pair(v.z);
            As[m4 + 3][k] = pack_pair(v.w);
        }
        #pragma unroll
        for (int p = 0; p < 8; p++) {
            int idx = p * 256 + tid;
            int k = idx & 31, n = idx >> 5;
            Bs[n][k] = wloc[n * 576 + k0 + k];
        }
        __syncthreads();

        {
            int kb = 0;
            uint2 bh0, bl0, bh1, bl1, bh2, bl2, bh3, bl3;
            LOADB_(Bs, 0, bh0, bl0); LOADB_(Bs, 1, bh1, bl1);
            LOADB_(Bs, 2, bh2, bl2); LOADB_(Bs, 3, bh3, bl3);
            MIBLOCK_(As, 0, c00, c01, c02, c03);
            MIBLOCK_(As, 1, c10, c11, c12, c13);
        }
        {
            int kb = 16;
            uint2 bh0, bl0, bh1, bl1, bh2, bl2, bh3, bl3;
            LOADB_(Bs, 0, bh0, bl0); LOADB_(Bs, 1, bh1, bl1);
            LOADB_(Bs, 2, bh2, bl2); LOADB_(Bs, 3, bh3, bl3);
            MIBLOCK_(As, 0, c00, c01, c02, c03);
            MIBLOCK_(As, 1, c10, c11, c12, c13);
        }
    }

    EPIF_(g_h3, 16, 0, 0, c00); EPIF_(g_h3, 16, 0, 1, c01);
    EPIF_(g_h3, 16, 0, 2, c02); EPIF_(g_h3, 16, 0, 3, c03);
    EPIF_(g_h3, 16, 1, 0, c10); EPIF_(g_h3, 16, 1, 1, c11);
    EPIF_(g_h3, 16, 1, 2, c12); EPIF_(g_h3, 16, 1, 3, c13);
}

// ---------------------------------------------------------------------------
// Linear head, fp32 h3 in.   [proven]
// ---------------------------------------------------------------------------
__global__ __launch_bounds__(256) void lin_k(const float* __restrict__ Wl,
                                             const float* __restrict__ blin,
                                             float* __restrict__ out) {
    const int CHUNK = 512;
    __shared__ float Wls[CHUNK * 10];
    __shared__ float sacc[8][32][10];

    int m0  = blockIdx.x * 32;
    int tid = threadIdx.x;
    int bl_ = tid % 32;
    int g   = tid / 32;

    float acc[10];
    #pragma unroll
    for (int t = 0; t < 10; t++) acc[t] = 0.f;

    for (int c = 0; c < 4; c++) {
        __syncthreads();
        for (int idx = tid; idx < CHUNK * 10; idx += 256) {
            int fl = idx / 10, t = idx % 10;
            Wls[idx] = Wl[t * 2048 + c * CHUNK + fl];
        }
        __syncthreads();
        int fbase = g * (CHUNK / 8);
        #pragma unroll 4
        for (int fl = fbase; fl < fbase + CHUNK / 8; fl++) {
            int f = c * CHUNK + fl;
            float v = g_h3[f * BATCH + m0 + bl_];
            const float* w = &Wls[fl * 10];
            #pragma unroll
            for (int t = 0; t < 10; t++) acc[t] = fmaf(v, w[t], acc[t]);
        }
    }
    #pragma unroll
    for (int t = 0; t < 10; t++) sacc[g][bl_][t] = acc[t];
    __syncthreads();
    for (int t2 = tid; t2 < 320; t2 += 256) {
        int bb = t2 / 10, t = t2 % 10;
        float s = blin[t];
        #pragma unroll
        for (int gg = 0; gg < 8; gg++) s += sacc[gg][bb][t];
        out[(m0 + bb) * 10 + t] = fmaxf(s, 0.f);
    }
}

// ---------------------------------------------------------------------------
extern "C" void kernel_launch(void* const* d_in, const int* in_sizes, int n_in,
                              void* d_out, int out_size) {
    const float* x  = (const float*)d_in[0];
    const float* W1 = (const float*)d_in[1];
    const float* b1 = (const float*)d_in[2];
    const float* W2 = (const float*)d_in[3];
    const float* b2 = (const float*)d_in[4];
    const float* W3 = (const float*)d_in[5];
    const float* b3 = (const float*)d_in[6];
    const float* Wl = (const float*)d_in[7];
    const float* bl = (const float*)d_in[8];
    float* out = (float*)d_out;

    transpose_x_k<<<dim3(25, 256), dim3(32, 8)>>>(x);
    wpack2_k<<<(36 * 64 * 288 + 255) / 256, 256>>>(W2);
    wpack3_k<<<(16 * 128 * 576 + 255) / 256, 256>>>(W3);
    ll1_k<<<dim3(169, 32), 256>>>(W1, b1);
    ll2_hmma_k<<<dim3(36, 64), 256>>>(b2);
    ll3_hmma_k<<<dim3(16, 64, 2), 256>>>(b3);
    lin_k<<<256, 256>>>(Wl, bl, out);
}

// round 13
// speedup vs baseline: 2.3742x; 1.7794x over previous
#include <cuda_runtime.h>
#include <cuda_bf16.h>
#include <cstdint>

// ---------------------------------------------------------------------------
// FreeConvNetwork, B=8192. LL2 + LL3 on mma.sync bf16 hi/lo-split tensor
// cores (fp32 accumulate). Proven-clean patterns only:
//   - pack/split ONLY in fills (registers) and standalone prep kernels
//   - hmma epilogues write fp32 ONLY (packed epilogues -> 384MiB lmem pool)
// NEW in this round: conflict-free smem. Tiles stored as pre-split fragment
// planes Ahi/Alo[k2][m], Bhi/Blo[k2][n] with XOR swizzle col ^= (k2&3)*8.
// Inner loop is pure LDS.32 + HMMA (no PRMT, no bank conflicts).
// value = hi + lo (bf16 each); D = Ahi*Bhi + Ahi*Blo + Alo*Bhi.
// ---------------------------------------------------------------------------

#define BATCH 8192

__device__ float    g_xT [784        * BATCH];   // (28*28, B)
__device__ float    g_h1 [32  * 169  * BATCH];   // fp32
__device__ float    g_h2 [64  * 36   * BATCH];   // fp32
__device__ float    g_h3 [2048       * BATCH];   // fp32
__device__ unsigned g_W2p[36 * 64  * 288];       // (loc, o, k) packed pairs
__device__ unsigned g_W3p[16 * 128 * 576];       // (loc, o, k) packed pairs

__device__ __forceinline__ unsigned pack_pair(float v) {
    __nv_bfloat16 h = __float2bfloat16(v);
    float r = v - __bfloat162float(h);
    __nv_bfloat16 l = __float2bfloat16(r);
    return ((unsigned)__bfloat16_as_ushort(l) << 16) | (unsigned)__bfloat16_as_ushort(h);
}

// Split two fp32 (consecutive k) into hi-fragment and lo-fragment u32s.
__device__ __forceinline__ void pack2(float a, float b, unsigned& hi, unsigned& lo) {
    __nv_bfloat16 ha = __float2bfloat16(a);
    __nv_bfloat16 hb = __float2bfloat16(b);
    float ra = a - __bfloat162float(ha);
    float rb = b - __bfloat162float(hb);
    __nv_bfloat16 la = __float2bfloat16(ra);
    __nv_bfloat16 lb = __float2bfloat16(rb);
    hi = ((unsigned)__bfloat16_as_ushort(hb) << 16) | (unsigned)__bfloat16_as_ushort(ha);
    lo = ((unsigned)__bfloat16_as_ushort(lb) << 16) | (unsigned)__bfloat16_as_ushort(la);
}

#define MMA(c, a0, a1, a2, a3, b) \
    asm volatile( \
        "mma.sync.aligned.m16n8k16.row.col.f32.bf16.bf16.f32 " \
        "{%0,%1,%2,%3}, {%4,%5,%6,%7}, {%8,%9}, {%0,%1,%2,%3};" \
        : "+f"(c.x), "+f"(c.y), "+f"(c.z), "+f"(c.w) \
        : "r"(a0), "r"(a1), "r"(a2), "r"(a3), "r"(b.x), "r"(b.y))

#define PERM_HI(x, y) __byte_perm(x, y, 0x5410)
#define PERM_LO(x, y) __byte_perm(x, y, 0x7632)

// ---------------------------------------------------------------------------
// x (B,784) -> xT (784,B)   [proven]
// ---------------------------------------------------------------------------
__global__ void transpose_x_k(const float* __restrict__ x) {
    __shared__ float tile[32][33];
    int c  = blockIdx.x * 32 + threadIdx.x;
    int r0 = blockIdx.y * 32;
    #pragma unroll
    for (int i = threadIdx.y; i < 32; i += 8) {
        int r = r0 + i;
        tile[i][threadIdx.x] = (c < 784) ? x[r * 784 + c] : 0.f;
    }
    __syncthreads();
    int oc  = r0 + threadIdx.x;
    int or0 = blockIdx.x * 32;
    #pragma unroll
    for (int i = threadIdx.y; i < 32; i += 8) {
        int orow = or0 + i;
        if (orow < 784) g_xT[orow * BATCH + oc] = tile[threadIdx.x][i];
    }
}

// ---------------------------------------------------------------------------
// Weight prep   [proven]
// ---------------------------------------------------------------------------
__global__ void wpack2_k(const float* __restrict__ W) {
    int idx = blockIdx.x * 256 + threadIdx.x;
    if (idx >= 36 * 64 * 288) return;
    int k   = idx % 288;
    int o   = (idx / 288) % 64;
    int loc = idx / (288 * 64);
    g_W2p[idx] = pack_pair(W[(o * 288 + k) * 36 + loc]);
}
__global__ void wpack3_k(const float* __restrict__ W) {
    int idx = blockIdx.x * 256 + threadIdx.x;
    if (idx >= 16 * 128 * 576) return;
    int k   = idx % 576;
    int o   = (idx / 576) % 128;
    int loc = idx / (576 * 128);
    g_W3p[idx] = pack_pair(W[(o * 576 + k) * 16 + loc]);
}

// ---------------------------------------------------------------------------
// LL1 (CUDA core, K=9), fp32 out.   [proven]
// ---------------------------------------------------------------------------
__global__ __launch_bounds__(256) void ll1_k(const float* __restrict__ W1,
                                             const float* __restrict__ b1) {
    int loc = blockIdx.x;
    int i = loc / 13, j = loc % 13;
    int b = blockIdx.y * 256 + threadIdx.x;

    __shared__ float ws[32 * 9];
    __shared__ float bs[32];
    for (int t = threadIdx.x; t < 32 * 9; t += 256) {
        int o = t / 9, k = t % 9;
        ws[t] = W1[(o * 9 + k) * 169 + loc];
    }
    if (threadIdx.x < 32) bs[threadIdx.x] = b1[threadIdx.x * 169 + loc];
    __syncthreads();

    float v[9];
    #pragma unroll
    for (int k = 0; k < 9; k++) {
        int di = k / 3, dj = k % 3;
        v[k] = g_xT[((2 * i + di) * 28 + (2 * j + dj)) * BATCH + b];
    }
    #pragma unroll
    for (int o = 0; o < 32; o++) {
        float acc = bs[o];
        #pragma unroll
        for (int k = 0; k < 9; k++) acc = fmaf(ws[o * 9 + k], v[k], acc);
        g_h1[(o * 169 + loc) * BATCH + b] = fmaxf(acc, 0.f);
    }
}

// ---------------------------------------------------------------------------
// hmma building-block macros (fragment planes + XOR swizzle).
// Fragment mapping (m16n8k16 row.col): a-reg j covers (m or m+8, k or k+8);
// k2 = k/2 indexes planes; swizzle s = (k2&3)*8, invariant under k2+4.
// ---------------------------------------------------------------------------
#define AFILL_(src) do { \
    _Pragma("unroll") \
    for (int p = 0; p < 2; p++) { \
        int k2 = p * 8 + wid; \
        int k  = k0 + k2 * 2; \
        int m4 = lane * 4; \
        float4 v0 = *(const float4*)(src + rowoffS[k]     + m0 + m4); \
        float4 v1 = *(const float4*)(src + rowoffS[k + 1] + m0 + m4); \
        uint4 hv, lv; \
        pack2(v0.x, v1.x, hv.x, lv.x); \
        pack2(v0.y, v1.y, hv.y, lv.y); \
        pack2(v0.z, v1.z, hv.z, lv.z); \
        pack2(v0.w, v1.w, hv.w, lv.w); \
        int sc = m4 ^ ((k2 & 3) * 8); \
        *(uint4*)&Ahi[k2][sc] = hv; \
        *(uint4*)&Alo[k2][sc] = lv; \
    } \
} while (0)

#define BFILL_(wloc, KREAL) do { \
    _Pragma("unroll") \
    for (int p = 0; p < 2; p++) { \
        int n  = p * 32 + (tid >> 3); \
        int k2 = (tid & 7) * 2; \
        uint4 q = *(const uint4*)(wloc + (size_t)n * (KREAL) + k0 + (tid & 7) * 4); \
        int s0 = (k2 & 3) * 8, s1 = ((k2 + 1) & 3) * 8; \
        Bhi[k2][n ^ s0]     = PERM_HI(q.x, q.y); \
        Blo[k2][n ^ s0]     = PERM_LO(q.x, q.y); \
        Bhi[k2 + 1][n ^ s1] = PERM_HI(q.z, q.w); \
        Blo[k2 + 1][n ^ s1] = PERM_LO(q.z, q.w); \
    } \
} while (0)

#define LOADB2_(NIv, bh, bl) do { \
    int _n  = wn * 32 + (NIv) * 8 + (lane >> 2); \
    int _k2 = kb2 + (lane & 3); \
    int _s  = (_k2 & 3) * 8; \
    bh.x = Bhi[_k2][_n ^ _s];  bh.y = Bhi[_k2 + 4][_n ^ _s]; \
    bl.x = Blo[_k2][_n ^ _s];  bl.y = Blo[_k2 + 4][_n ^ _s]; \
} while (0)

#define MIBLOCK2_(MI, c0, c1, c2, c3) do { \
    int _m  = wm * 32 + (MI) * 16 + (lane >> 2); \
    int _k2 = kb2 + (lane & 3); \
    int _s  = (_k2 & 3) * 8; \
    unsigned ah0 = Ahi[_k2][_m ^ _s],     ah1 = Ahi[_k2][(_m + 8) ^ _s]; \
    unsigned ah2 = Ahi[_k2 + 4][_m ^ _s], ah3 = Ahi[_k2 + 4][(_m + 8) ^ _s]; \
    unsigned al0 = Alo[_k2][_m ^ _s],     al1 = Alo[_k2][(_m + 8) ^ _s]; \
    unsigned al2 = Alo[_k2 + 4][_m ^ _s], al3 = Alo[_k2 + 4][(_m + 8) ^ _s]; \
    MMA(c0, ah0, ah1, ah2, ah3, bh0); \
    MMA(c0, ah0, ah1, ah2, ah3, bl0); \
    MMA(c0, al0, al1, al2, al3, bh0); \
    MMA(c1, ah0, ah1, ah2, ah3, bh1); \
    MMA(c1, ah0, ah1, ah2, ah3, bl1); \
    MMA(c1, al0, al1, al2, al3, bh1); \
    MMA(c2, ah0, ah1, ah2, ah3, bh2); \
    MMA(c2, ah0, ah1, ah2, ah3, bl2); \
    MMA(c2, al0, al1, al2, al3, bh2); \
    MMA(c3, ah0, ah1, ah2, ah3, bh3); \
    MMA(c3, ah0, ah1, ah2, ah3, bl3); \
    MMA(c3, al0, al1, al2, al3, bh3); \
} while (0)

#define KSTEP_() do { \
    uint2 bh0, bl0, bh1, bl1, bh2, bl2, bh3, bl3; \
    LOADB2_(0, bh0, bl0); LOADB2_(1, bh1, bl1); \
    LOADB2_(2, bh2, bl2); LOADB2_(3, bh3, bl3); \
    MIBLOCK2_(0, c00, c01, c02, c03); \
    MIBLOCK2_(1, c10, c11, c12, c13); \
} while (0)

// fp32 epilogue ONLY.   [proven]
#define EPIF_(dst, LOCS, MI, NIv, c) do { \
    int _m = m0 + wm * 32 + (MI) * 16 + (lane >> 2); \
    int _ol = wn * 32 + (NIv) * 8 + (lane & 3) * 2; \
    int _o  = n0 + _ol; \
    float _b0 = biasS[_ol], _b1 = biasS[_ol + 1]; \
    size_t _ba0 = (size_t)(_o * (LOCS) + loc) * BATCH; \
    size_t _ba1 = (size_t)((_o + 1) * (LOCS) + loc) * BATCH; \
    dst[_ba0 + _m]     = fmaxf(c.x + _b0, 0.f); \
    dst[_ba1 + _m]     = fmaxf(c.y + _b1, 0.f); \
    dst[_ba0 + _m + 8] = fmaxf(c.z + _b0, 0.f); \
    dst[_ba1 + _m + 8] = fmaxf(c.w + _b1, 0.f); \
} while (0)

// ---------------------------------------------------------------------------
// LL2 on mma.sync. N=64, K=288, 36 locs. CTA=(loc, 128-batch); 8 warps 4m x 2n.
// ---------------------------------------------------------------------------
__global__ __launch_bounds__(256, 1) void ll2_hmma_k(const float* __restrict__ b2) {
    __shared__ unsigned Ahi[16][128], Alo[16][128];
    __shared__ unsigned Bhi[16][64],  Blo[16][64];
    __shared__ int   rowoffS[288];
    __shared__ float biasS[64];

    int tid  = threadIdx.x;
    int lane = tid & 31;
    int wid  = tid >> 5;
    int wn   = wid & 1;
    int wm   = wid >> 1;
    int loc  = blockIdx.x;
    int m0   = blockIdx.y * 128;
    const int n0 = 0;
    int li = loc / 6, lj = loc % 6;

    for (int k = tid; k < 288; k += 256) {
        int c = k / 9, r = (k % 9) / 3, cc = k % 3;
        rowoffS[k] = (c * 169 + (2 * li + r) * 13 + (2 * lj + cc)) * BATCH;
    }
    if (tid < 64) biasS[tid] = b2[tid * 36 + loc];

    float4 c00 = {0,0,0,0}, c01 = {0,0,0,0}, c02 = {0,0,0,0}, c03 = {0,0,0,0};
    float4 c10 = {0,0,0,0}, c11 = {0,0,0,0}, c12 = {0,0,0,0}, c13 = {0,0,0,0};

    const unsigned* wloc = g_W2p + (size_t)loc * 64 * 288;

    for (int k0 = 0; k0 < 288; k0 += 32) {
        __syncthreads();
        AFILL_(g_h1);
        BFILL_(wloc, 288);
        __syncthreads();
        { int kb2 = 0; KSTEP_(); }
        { int kb2 = 8; KSTEP_(); }
    }

    EPIF_(g_h2, 36, 0, 0, c00); EPIF_(g_h2, 36, 0, 1, c01);
    EPIF_(g_h2, 36, 0, 2, c02); EPIF_(g_h2, 36, 0, 3, c03);
    EPIF_(g_h2, 36, 1, 0, c10); EPIF_(g_h2, 36, 1, 1, c11);
    EPIF_(g_h2, 36, 1, 2, c12); EPIF_(g_h2, 36, 1, 3, c13);
}

// ---------------------------------------------------------------------------
// LL3 on mma.sync. N=128 (n0 via grid.z), K=576, 16 locs.
// ---------------------------------------------------------------------------
__global__ __launch_bounds__(256, 1) void ll3_hmma_k(const float* __restrict__ b3) {
    __shared__ unsigned Ahi[16][128], Alo[16][128];
    __shared__ unsigned Bhi[16][64],  Blo[16][64];
    __shared__ int   rowoffS[576];
    __shared__ float biasS[64];

    int tid  = threadIdx.x;
    int lane = tid & 31;
    int wid  = tid >> 5;
    int wn   = wid & 1;
    int wm   = wid >> 1;
    int loc  = blockIdx.x;
    int m0   = blockIdx.y * 128;
    int n0   = blockIdx.z * 64;
    int li = loc / 4, lj = loc % 4;

    for (int k = tid; k < 576; k += 256) {
        int c = k / 9, r = (k % 9) / 3, cc = k % 3;
        rowoffS[k] = (c * 36 + (li + r) * 6 + (lj + cc)) * BATCH;
    }
    if (tid < 64) biasS[tid] = b3[(n0 + tid) * 16 + loc];

    float4 c00 = {0,0,0,0}, c01 = {0,0,0,0}, c02 = {0,0,0,0}, c03 = {0,0,0,0};
    float4 c10 = {0,0,0,0}, c11 = {0,0,0,0}, c12 = {0,0,0,0}, c13 = {0,0,0,0};

    const unsigned* wloc = g_W3p + (size_t)loc * 128 * 576 + (size_t)n0 * 576;

    for (int k0 = 0; k0 < 576; k0 += 32) {
        __syncthreads();
        AFILL_(g_h2);
        BFILL_(wloc, 576);
        __syncthreads();
        { int kb2 = 0; KSTEP_(); }
        { int kb2 = 8; KSTEP_(); }
    }

    EPIF_(g_h3, 16, 0, 0, c00); EPIF_(g_h3, 16, 0, 1, c01);
    EPIF_(g_h3, 16, 0, 2, c02); EPIF_(g_h3, 16, 0, 3, c03);
    EPIF_(g_h3, 16, 1, 0, c10); EPIF_(g_h3, 16, 1, 1, c11);
    EPIF_(g_h3, 16, 1, 2, c12); EPIF_(g_h3, 16, 1, 3, c13);
}

// ---------------------------------------------------------------------------
// Linear head, fp32 h3 in.   [proven]
// ---------------------------------------------------------------------------
__global__ __launch_bounds__(256) void lin_k(const float* __restrict__ Wl,
                                             const float* __restrict__ blin,
                                             float* __restrict__ out) {
    const int CHUNK = 512;
    __shared__ float Wls[CHUNK * 10];
    __shared__ float sacc[8][32][10];

    int m0  = blockIdx.x * 32;
    int tid = threadIdx.x;
    int bl_ = tid % 32;
    int g   = tid / 32;

    float acc[10];
    #pragma unroll
    for (int t = 0; t < 10; t++) acc[t] = 0.f;

    for (int c = 0; c < 4; c++) {
        __syncthreads();
        for (int idx = tid; idx < CHUNK * 10; idx += 256) {
            int fl = idx / 10, t = idx % 10;
            Wls[idx] = Wl[t * 2048 + c * CHUNK + fl];
        }
        __syncthreads();
        int fbase = g * (CHUNK / 8);
        #pragma unroll 4
        for (int fl = fbase; fl < fbase + CHUNK / 8; fl++) {
            int f = c * CHUNK + fl;
            float v = g_h3[f * BATCH + m0 + bl_];
            const float* w = &Wls[fl * 10];
            #pragma unroll
            for (int t = 0; t < 10; t++) acc[t] = fmaf(v, w[t], acc[t]);
        }
    }
    #pragma unroll
    for (int t = 0; t < 10; t++) sacc[g][bl_][t] = acc[t];
    __syncthreads();
    for (int t2 = tid; t2 < 320; t2 += 256) {
        int bb = t2 / 10, t = t2 % 10;
        float s = blin[t];
        #pragma unroll
        for (int gg = 0; gg < 8; gg++) s += sacc[gg][bb][t];
        out[(m0 + bb) * 10 + t] = fmaxf(s, 0.f);
    }
}

// ---------------------------------------------------------------------------
extern "C" void kernel_launch(void* const* d_in, const int* in_sizes, int n_in,
                              void* d_out, int out_size) {
    const float* x  = (const float*)d_in[0];
    const float* W1 = (const float*)d_in[1];
    const float* b1 = (const float*)d_in[2];
    const float* W2 = (const float*)d_in[3];
    const float* b2 = (const float*)d_in[4];
    const float* W3 = (const float*)d_in[5];
    const float* b3 = (const float*)d_in[6];
    const float* Wl = (const float*)d_in[7];
    const float* bl = (const float*)d_in[8];
    float* out = (float*)d_out;

    transpose_x_k<<<dim3(25, 256), dim3(32, 8)>>>(x);
    wpack2_k<<<(36 * 64 * 288 + 255) / 256, 256>>>(W2);
    wpack3_k<<<(16 * 128 * 576 + 255) / 256, 256>>>(W3);
    ll1_k<<<dim3(169, 32), 256>>>(W1, b1);
    ll2_hmma_k<<<dim3(36, 64), 256>>>(b2);
    ll3_hmma_k<<<dim3(16, 64, 2), 256>>>(b3);
    lin_k<<<256, 256>>>(Wl, bl, out);
}